// round 14
// baseline (speedup 1.0000x reference)
#include <cuda_runtime.h>

#define NDIM 65
#define ND2  4225
#define NV   274625
#define NVB  1073            /* 256-vertex blocks            */
#define NC   262144          /* 64^3 cubes                   */
#define NCB  1024            /* cube blocks of 256           */
#define NBLK (NVB + NCB)     /* 2097 blocks in fused kernels */

// -------- scratch (device globals; no allocations allowed) --------
__device__ unsigned int       g_pkl[NV];      // (block-local excl << 7) | mask
__device__ int                g_vblk[NVB+1];  // block totals -> scanned bases (+M)
__device__ unsigned char      g_occ8[NC];     // per-cube 8-bit occupancy
__device__ unsigned long long g_tblk[NCB];    // lo32=c1 base, hi32=c2 base
__device__ int                g_M;
__device__ int                g_F1;

__device__ const signed char d_tri[96] = {
  -1,-1,-1,-1,-1,-1,  1,0,2,-1,-1,-1,  4,0,3,-1,-1,-1,  1,4,2,1,3,4,
   3,1,5,-1,-1,-1,    2,3,0,2,5,3,     1,4,0,1,5,4,     4,2,5,-1,-1,-1,
   4,5,2,-1,-1,-1,    4,1,0,4,5,1,     3,2,0,3,5,2,     1,3,5,-1,-1,-1,
   4,1,2,4,3,1,       3,0,4,-1,-1,-1,  2,0,1,-1,-1,-1, -1,-1,-1,-1,-1,-1};
__device__ const signed char d_ea[6]   = {0,0,0,1,1,2};
__device__ const signed char d_eb[6]   = {1,2,3,2,3,3};
__device__ const signed char d_kuhn[24] = {0,1,3,7, 0,3,2,7, 0,2,6,7,
                                           0,6,4,7, 0,4,5,7, 0,5,1,7};

__device__ __forceinline__ int corner_off(int b) {
    return (b & 1) * ND2 + ((b >> 1) & 1) * NDIM + ((b >> 2) & 1);
}

// ---------------- warp-shuffle block scan (256 threads) ----------------
template <typename T>
__device__ __forceinline__ T blockScanExcl256(T val, T& total) {
    unsigned lane = threadIdx.x & 31, w = threadIdx.x >> 5;
    T incl = val;
    #pragma unroll
    for (int o = 1; o < 32; o <<= 1) {
        T n = __shfl_up_sync(0xffffffffu, incl, o);
        if (lane >= o) incl += n;
    }
    __shared__ T ws[8];
    if (lane == 31) ws[w] = incl;
    __syncthreads();
    if (w == 0) {
        T x = (lane < 8) ? ws[lane] : T(0);
        #pragma unroll
        for (int o = 1; o < 8; o <<= 1) {
            T n = __shfl_up_sync(0xffffffffu, x, o);
            if (lane >= o) x += n;
        }
        if (lane < 8) ws[lane] = x;
    }
    __syncthreads();
    T base = (w > 0) ? ws[w - 1] : T(0);
    total = ws[7];
    return base + incl - val;
}

// per-cube tet codes from occ byte: packed (lo16=#1tri, hi16=#2tri), fills ti6[]
__device__ __forceinline__ unsigned cube_codes(unsigned occ8, int* ti6) {
    const int ka[6] = {1,3,2,6,4,5};
    const int kb[6] = {3,2,6,4,5,1};
    unsigned sum = 0;
    #pragma unroll
    for (int ku = 0; ku < 6; ++ku) {
        int ti = (int)(occ8 & 1u)
               | (int)(((occ8 >> ka[ku]) & 1u) << 1)
               | (int)(((occ8 >> kb[ku]) & 1u) << 2)
               | (int)(((occ8 >> 7) & 1u) << 3);
        ti6[ku] = ti;
        int pc = __popc(ti);
        int nt = min(pc, 4 - pc);
        sum += (nt == 1) ? 1u : ((nt == 2) ? 0x10000u : 0u);
    }
    return sum;
}

// ================= kCount: fused vertex masks + tet class counts (R10) =================
__global__ void kCount(const float* __restrict__ level, const int* __restrict__ thrp) {
    float thr = (float)thrp[0];
    if (blockIdx.x < NVB) {
        // ---- vertex branch ----
        int v = blockIdx.x * 256 + threadIdx.x;
        unsigned int mask = 0;
        if (v < NV) {
            int i = v / ND2;
            int r = v - i * ND2;
            int j = r / NDIM;
            int k = r - j * NDIM;
            bool o0 = (level[v] - thr) > 0.0f;
            #pragma unroll
            for (int d = 1; d < 8; ++d) {
                int di = d >> 2, dj = (d >> 1) & 1, dk = d & 1;
                if (i + di < NDIM && j + dj < NDIM && k + dk < NDIM) {
                    bool o1 = (level[v + di * ND2 + dj * NDIM + dk] - thr) > 0.0f;
                    if (o0 != o1) mask |= 1u << (d - 1);
                }
            }
        }
        int cnt = __popc(mask);
        int total;
        int excl = blockScanExcl256<int>(cnt, total);
        if (v < NV) g_pkl[v] = ((unsigned)excl << 7) | mask;
        if (threadIdx.x == 0) g_vblk[blockIdx.x] = total;
    } else {
        // ---- cube branch: classify tets straight from level, store occ8 ----
        int cb = blockIdx.x - NVB;
        int cube = cb * 256 + threadIdx.x;
        int ci = cube >> 12, cj = (cube >> 6) & 63, ck = cube & 63;
        int v000 = (ci * NDIM + cj) * NDIM + ck;
        unsigned occ8 = 0;
        #pragma unroll
        for (int b = 0; b < 8; ++b)
            occ8 |= ((level[v000 + corner_off(b)] - thr) > 0.0f ? 1u : 0u) << b;
        g_occ8[cube] = (unsigned char)occ8;
        int ti6[6];
        unsigned sum = cube_codes(occ8, ti6);

        #pragma unroll
        for (int o = 16; o > 0; o >>= 1) sum += __shfl_down_sync(0xffffffffu, sum, o);
        __shared__ unsigned ws[8];
        unsigned lane = threadIdx.x & 31, w = threadIdx.x >> 5;
        if (lane == 0) ws[w] = sum;
        __syncthreads();
        if (threadIdx.x == 0) {
            unsigned tot = 0;
            #pragma unroll
            for (int x = 0; x < 8; ++x) tot += ws[x];
            g_tblk[cb] = (unsigned long long)(tot & 0xFFFFu)
                       | ((unsigned long long)(tot >> 16) << 32);
        }
    }
}

// ================= kScan: both small scans =================
__global__ void kScan() {
    int t = threadIdx.x;
    unsigned lane = t & 31, w = t >> 5;

    { // vertex block bases (1073 ints, 2/thread)
        int i0 = 2 * t, i1 = 2 * t + 1;
        int e0 = (i0 < NVB) ? g_vblk[i0] : 0;
        int e1 = (i1 < NVB) ? g_vblk[i1] : 0;
        int val = e0 + e1;
        int incl = val;
        #pragma unroll
        for (int o = 1; o < 32; o <<= 1) {
            int n = __shfl_up_sync(0xffffffffu, incl, o);
            if (lane >= o) incl += n;
        }
        __shared__ int wsA[32];
        if (lane == 31) wsA[w] = incl;
        __syncthreads();
        if (w == 0) {
            int x = wsA[lane];
            #pragma unroll
            for (int o = 1; o < 32; o <<= 1) {
                int n = __shfl_up_sync(0xffffffffu, x, o);
                if (lane >= o) x += n;
            }
            wsA[lane] = x;
        }
        __syncthreads();
        int excl = ((w > 0) ? wsA[w - 1] : 0) + incl - val;
        if (i0 < NVB) g_vblk[i0] = excl;
        if (i1 < NVB) g_vblk[i1] = excl + e0;
        if (t == 1023) { g_M = excl + val; g_vblk[NVB] = excl + val; }
        __syncthreads();
    }

    { // tet block bases (1024 u64)
        unsigned long long val = g_tblk[t];
        unsigned long long incl = val;
        #pragma unroll
        for (int o = 1; o < 32; o <<= 1) {
            unsigned long long n = __shfl_up_sync(0xffffffffu, incl, o);
            if (lane >= o) incl += n;
        }
        __shared__ unsigned long long wsB[32];
        if (lane == 31) wsB[w] = incl;
        __syncthreads();
        if (w == 0) {
            unsigned long long x = wsB[lane];
            #pragma unroll
            for (int o = 1; o < 32; o <<= 1) {
                unsigned long long n = __shfl_up_sync(0xffffffffu, x, o);
                if (lane >= o) x += n;
            }
            wsB[lane] = x;
        }
        __syncthreads();
        unsigned long long excl = ((w > 0) ? wsB[w - 1] : 0ull) + incl - val;
        g_tblk[t] = excl;
        if (t == 1023) g_F1 = (int)((excl + val) & 0xFFFFFFFFull);
    }
}

// ================= kEmit: fused verts + faces, half-pass staging =================
__global__ void __launch_bounds__(256, 6)
kEmit(const float* __restrict__ level, const int* __restrict__ thrp,
      float* __restrict__ out) {
    __shared__ __align__(16) float s_stage[4608];   // 18 KB half-buffer
    __shared__ unsigned       s_pack[8 * 256];      // 8 KB corner cache
    __shared__ unsigned short s_ptab[768];          // fused (ku,ti) table
    __shared__ unsigned       s_half;               // half-boundary broadcast

    int tid = threadIdx.x;
    if (blockIdx.x < NVB) {
        // ---- emit vertices in two half-passes of 128 ----
        int v = blockIdx.x * 256 + tid;
        unsigned pk = (v < NV) ? g_pkl[v] : 0u;
        unsigned mask = pk & 0x7Fu;
        int excl = (int)(pk >> 7);
        int gbase = g_vblk[blockIdx.x];
        int total = g_vblk[blockIdx.x + 1] - gbase;
        if (tid == 128) s_half = (unsigned)excl;
        __syncthreads();
        int h = (int)s_half;            // verts in first half

        float thr = (float)thrp[0];
        const float inv = 1.0f / 64.0f;

        #pragma unroll
        for (int ph = 0; ph < 2; ++ph) {
            bool mine = (ph == 0) ? (tid < 128) : (tid >= 128);
            if (mine && mask) {
                int i = v / ND2;
                int r = v - i * ND2;
                int j = r / NDIM;
                int k = r - j * NDIM;
                float s0  = level[v] - thr;
                float p0x = (float)i * inv, p0y = (float)j * inv, p0z = (float)k * inv;
                int sp = 3 * (excl - (ph ? h : 0));
                #pragma unroll
                for (int d = 1; d < 8; ++d) {
                    if (mask & (1u << (d - 1))) {
                        int di = d >> 2, dj = (d >> 1) & 1, dk = d & 1;
                        int w = v + di * ND2 + dj * NDIM + dk;
                        float s1 = level[w] - thr;
                        float rdenom = 1.0f / (s0 - s1);
                        float w0 = (-s1) * rdenom;
                        float w1 = s0 * rdenom;
                        s_stage[sp + 0] = p0x * w0 + (float)(i + di) * inv * w1;
                        s_stage[sp + 1] = p0y * w0 + (float)(j + dj) * inv * w1;
                        s_stage[sp + 2] = p0z * w0 + (float)(k + dk) * inv * w1;
                        sp += 3;
                    }
                }
            }
            __syncthreads();
            int base = ph ? h : 0;
            int cnt3 = 3 * ((ph ? total : h) - base);
            float* dst = out + 3ll * (gbase + base);
            for (int x = tid; x < cnt3; x += 256) dst[x] = s_stage[x];
            __syncthreads();
        }
    } else {
        // ---- emit faces in two half-passes of 128 cubes ----
        if (tid < 96) {
            int ku = tid >> 4, ti = tid & 15;
            #pragma unroll
            for (int s = 0; s < 6; ++s) {
                int le = d_tri[ti * 6 + s];
                unsigned short pv = 0;
                if (le >= 0) {
                    int ba = d_kuhn[ku * 4 + d_ea[le]];
                    int bb = d_kuhn[ku * 4 + d_eb[le]];
                    int lo = ba & bb;
                    int dd = ba ^ bb;
                    int bit = (((dd & 1) << 2) | (dd & 2) | ((dd >> 2) & 1)) - 1;
                    pv = (unsigned short)((lo << 3) | bit);
                }
                s_ptab[(ku * 16 + ti) * 8 + s] = pv;
            }
        }

        int cb = blockIdx.x - NVB;
        int cube = cb * 256 + tid;
        int ci = cube >> 12, cj = (cube >> 6) & 63, ck = cube & 63;
        int v000 = (ci * NDIM + cj) * NDIM + ck;
        unsigned occ8 = (unsigned)g_occ8[cube];
        int ti6[6];
        unsigned sum = cube_codes(occ8, ti6);

        // corner cache with global vertex base folded in
        #pragma unroll
        for (int c = 0; c < 8; ++c) {
            int vc = v000 + corner_off(c);
            unsigned pk = g_pkl[vc];
            s_pack[c * 256 + tid] =
                (((unsigned)g_vblk[vc >> 8] + (pk >> 7)) << 7) | (pk & 0x7Fu);
        }

        unsigned total;
        unsigned run = blockScanExcl256<unsigned>(sum, total);  // syncs cover s_* writes
        if (tid == 128) s_half = run;
        __syncthreads();
        unsigned hf = s_half;
        int T1a = (int)(hf & 0xFFFFu),     T2a = (int)(hf >> 16);
        int T1t = (int)(total & 0xFFFFu),  T2t = (int)(total >> 16);
        int T1b = T1t - T1a,               T2b = T2t - T2a;

        unsigned long long blk = g_tblk[cb];
        int c1base = (int)(blk & 0xFFFFFFFFull);
        int c2base = (int)(blk >> 32);
        float* fout = out + 3ll * g_M;
        float* dst1 = fout + 3ll * c1base;
        float* dst2 = fout + 3ll * (g_F1 + 2ll * c2base);

        #pragma unroll
        for (int ph = 0; ph < 2; ++ph) {
            bool mine = (ph == 0) ? (tid < 128) : (tid >= 128);
            int T1h = ph ? T1b : T1a;
            if (mine) {
                unsigned r = ph ? (run - hf) : run;   // borrow-free (monotone halves)
                #pragma unroll
                for (int ku = 0; ku < 6; ++ku) {
                    int ti = ti6[ku];
                    int pc = __popc(ti);
                    int nt = min(pc, 4 - pc);
                    if (nt == 0) continue;
                    int sp;
                    unsigned code;
                    if (nt == 1) { sp = 3 * (int)(r & 0xFFFFu);          code = 1u; }
                    else         { sp = 3 * T1h + 6 * (int)(r >> 16);    code = 0x10000u; }
                    const unsigned short* pt = &s_ptab[(ku * 16 + ti) * 8];
                    int nent = 3 * nt;
                    for (int e = 0; e < nent; ++e) {
                        unsigned pe = pt[e];
                        unsigned pk = s_pack[(pe >> 3) * 256 + tid];
                        int vidx = (int)(pk >> 7)
                                 + __popc(pk & 0x7Fu & ((1u << (pe & 7)) - 1u));
                        s_stage[sp + e] = (float)vidx;
                    }
                    r += code;
                }
            }
            __syncthreads();
            // copy out this half: 1-tri entries then 2-tri entries
            {
                float* d1 = dst1 + 3 * (ph ? T1a : 0);
                int n1 = 3 * T1h;
                for (int x = tid; x < n1; x += 256) d1[x] = s_stage[x];
                float* d2 = dst2 + 6 * (ph ? T2a : 0);
                int n2 = 6 * (ph ? T2b : T2a);
                const float* src2 = s_stage + n1;
                for (int x = tid; x < n2; x += 256) d2[x] = src2[x];
            }
            __syncthreads();
        }
    }
}

// ---------------- launch ----------------
extern "C" void kernel_launch(void* const* d_in, const int* in_sizes, int n_in,
                              void* d_out, int out_size) {
    const float* level = (const float*)d_in[0];
    const int*   thrp  = (const int*)d_in[3];
    float*       out   = (float*)d_out;
    (void)in_sizes; (void)n_in; (void)out_size;

    kCount<<<NBLK, 256>>>(level, thrp);
    kScan <<<1, 1024>>>();
    kEmit <<<NBLK, 256>>>(level, thrp, out);
}

// round 15
// speedup vs baseline: 1.4019x; 1.4019x over previous
#include <cuda_runtime.h>

#define NDIM 65
#define ND2  4225
#define NV   274625
#define NVB  1073            /* 256-vertex blocks            */
#define NC   262144          /* 64^3 cubes                   */
#define NCB  1024            /* cube blocks of 256           */
#define NBLK (NVB + NCB)     /* 2097 blocks in fused kernels */

// -------- scratch (device globals; no allocations allowed) --------
__device__ unsigned int       g_pkl[NV];      // (block-local excl << 7) | mask
__device__ int                g_vblk[NVB+1];  // block totals -> scanned bases (+M)
__device__ unsigned char      g_occ8[NC];     // per-cube 8-bit occupancy
__device__ unsigned long long g_tblk[NCB];    // lo32=c1 base, hi32=c2 base
__device__ int                g_M;
__device__ int                g_F1;

__device__ const signed char d_tri[96] = {
  -1,-1,-1,-1,-1,-1,  1,0,2,-1,-1,-1,  4,0,3,-1,-1,-1,  1,4,2,1,3,4,
   3,1,5,-1,-1,-1,    2,3,0,2,5,3,     1,4,0,1,5,4,     4,2,5,-1,-1,-1,
   4,5,2,-1,-1,-1,    4,1,0,4,5,1,     3,2,0,3,5,2,     1,3,5,-1,-1,-1,
   4,1,2,4,3,1,       3,0,4,-1,-1,-1,  2,0,1,-1,-1,-1, -1,-1,-1,-1,-1,-1};
__device__ const signed char d_ea[6]   = {0,0,0,1,1,2};
__device__ const signed char d_eb[6]   = {1,2,3,2,3,3};
__device__ const signed char d_kuhn[24] = {0,1,3,7, 0,3,2,7, 0,2,6,7,
                                           0,6,4,7, 0,4,5,7, 0,5,1,7};

__device__ __forceinline__ int corner_off(int b) {
    return (b & 1) * ND2 + ((b >> 1) & 1) * NDIM + ((b >> 2) & 1);
}

// ---------------- warp-shuffle block scan (256 threads) ----------------
template <typename T>
__device__ __forceinline__ T blockScanExcl256(T val, T& total) {
    unsigned lane = threadIdx.x & 31, w = threadIdx.x >> 5;
    T incl = val;
    #pragma unroll
    for (int o = 1; o < 32; o <<= 1) {
        T n = __shfl_up_sync(0xffffffffu, incl, o);
        if (lane >= o) incl += n;
    }
    __shared__ T ws[8];
    if (lane == 31) ws[w] = incl;
    __syncthreads();
    if (w == 0) {
        T x = (lane < 8) ? ws[lane] : T(0);
        #pragma unroll
        for (int o = 1; o < 8; o <<= 1) {
            T n = __shfl_up_sync(0xffffffffu, x, o);
            if (lane >= o) x += n;
        }
        if (lane < 8) ws[lane] = x;
    }
    __syncthreads();
    T base = (w > 0) ? ws[w - 1] : T(0);
    total = ws[7];
    return base + incl - val;
}

// per-cube tet codes from occ byte: packed (lo16=#1tri, hi16=#2tri), fills ti6[]
__device__ __forceinline__ unsigned cube_codes(unsigned occ8, int* ti6) {
    const int ka[6] = {1,3,2,6,4,5};
    const int kb[6] = {3,2,6,4,5,1};
    unsigned sum = 0;
    #pragma unroll
    for (int ku = 0; ku < 6; ++ku) {
        int ti = (int)(occ8 & 1u)
               | (int)(((occ8 >> ka[ku]) & 1u) << 1)
               | (int)(((occ8 >> kb[ku]) & 1u) << 2)
               | (int)(((occ8 >> 7) & 1u) << 3);
        ti6[ku] = ti;
        int pc = __popc(ti);
        int nt = min(pc, 4 - pc);
        sum += (nt == 1) ? 1u : ((nt == 2) ? 0x10000u : 0u);
    }
    return sum;
}

// ================= kCount: fused vertex masks + tet class counts (R10) =================
__global__ void kCount(const float* __restrict__ level, const int* __restrict__ thrp) {
    float thr = (float)thrp[0];
    if (blockIdx.x < NVB) {
        // ---- vertex branch ----
        int v = blockIdx.x * 256 + threadIdx.x;
        unsigned int mask = 0;
        if (v < NV) {
            int i = v / ND2;
            int r = v - i * ND2;
            int j = r / NDIM;
            int k = r - j * NDIM;
            bool o0 = (level[v] - thr) > 0.0f;
            #pragma unroll
            for (int d = 1; d < 8; ++d) {
                int di = d >> 2, dj = (d >> 1) & 1, dk = d & 1;
                if (i + di < NDIM && j + dj < NDIM && k + dk < NDIM) {
                    bool o1 = (level[v + di * ND2 + dj * NDIM + dk] - thr) > 0.0f;
                    if (o0 != o1) mask |= 1u << (d - 1);
                }
            }
        }
        int cnt = __popc(mask);
        int total;
        int excl = blockScanExcl256<int>(cnt, total);
        if (v < NV) g_pkl[v] = ((unsigned)excl << 7) | mask;
        if (threadIdx.x == 0) g_vblk[blockIdx.x] = total;
    } else {
        // ---- cube branch: classify tets straight from level, store occ8 ----
        int cb = blockIdx.x - NVB;
        int cube = cb * 256 + threadIdx.x;
        int ci = cube >> 12, cj = (cube >> 6) & 63, ck = cube & 63;
        int v000 = (ci * NDIM + cj) * NDIM + ck;
        unsigned occ8 = 0;
        #pragma unroll
        for (int b = 0; b < 8; ++b)
            occ8 |= ((level[v000 + corner_off(b)] - thr) > 0.0f ? 1u : 0u) << b;
        g_occ8[cube] = (unsigned char)occ8;
        int ti6[6];
        unsigned sum = cube_codes(occ8, ti6);

        #pragma unroll
        for (int o = 16; o > 0; o >>= 1) sum += __shfl_down_sync(0xffffffffu, sum, o);
        __shared__ unsigned ws[8];
        unsigned lane = threadIdx.x & 31, w = threadIdx.x >> 5;
        if (lane == 0) ws[w] = sum;
        __syncthreads();
        if (threadIdx.x == 0) {
            unsigned tot = 0;
            #pragma unroll
            for (int x = 0; x < 8; ++x) tot += ws[x];
            g_tblk[cb] = (unsigned long long)(tot & 0xFFFFu)
                       | ((unsigned long long)(tot >> 16) << 32);
        }
    }
}

// ================= kScan: both small scans =================
__global__ void kScan() {
    int t = threadIdx.x;
    unsigned lane = t & 31, w = t >> 5;

    { // vertex block bases (1073 ints, 2/thread)
        int i0 = 2 * t, i1 = 2 * t + 1;
        int e0 = (i0 < NVB) ? g_vblk[i0] : 0;
        int e1 = (i1 < NVB) ? g_vblk[i1] : 0;
        int val = e0 + e1;
        int incl = val;
        #pragma unroll
        for (int o = 1; o < 32; o <<= 1) {
            int n = __shfl_up_sync(0xffffffffu, incl, o);
            if (lane >= o) incl += n;
        }
        __shared__ int wsA[32];
        if (lane == 31) wsA[w] = incl;
        __syncthreads();
        if (w == 0) {
            int x = wsA[lane];
            #pragma unroll
            for (int o = 1; o < 32; o <<= 1) {
                int n = __shfl_up_sync(0xffffffffu, x, o);
                if (lane >= o) x += n;
            }
            wsA[lane] = x;
        }
        __syncthreads();
        int excl = ((w > 0) ? wsA[w - 1] : 0) + incl - val;
        if (i0 < NVB) g_vblk[i0] = excl;
        if (i1 < NVB) g_vblk[i1] = excl + e0;
        if (t == 1023) { g_M = excl + val; g_vblk[NVB] = excl + val; }
        __syncthreads();
    }

    { // tet block bases (1024 u64)
        unsigned long long val = g_tblk[t];
        unsigned long long incl = val;
        #pragma unroll
        for (int o = 1; o < 32; o <<= 1) {
            unsigned long long n = __shfl_up_sync(0xffffffffu, incl, o);
            if (lane >= o) incl += n;
        }
        __shared__ unsigned long long wsB[32];
        if (lane == 31) wsB[w] = incl;
        __syncthreads();
        if (w == 0) {
            unsigned long long x = wsB[lane];
            #pragma unroll
            for (int o = 1; o < 32; o <<= 1) {
                unsigned long long n = __shfl_up_sync(0xffffffffu, x, o);
                if (lane >= o) x += n;
            }
            wsB[lane] = x;
        }
        __syncthreads();
        unsigned long long excl = ((w > 0) ? wsB[w - 1] : 0ull) + incl - val;
        g_tblk[t] = excl;
        if (t == 1023) g_F1 = (int)((excl + val) & 0xFFFFFFFFull);
    }
}

// ================= kEmit: staged verts + scattered faces, small smem =================
__global__ void __launch_bounds__(256)
kEmit(const float* __restrict__ level, const int* __restrict__ thrp,
      float* __restrict__ out) {
    // union: vertex branch uses it as float stage (5376); face branch as pack cache (2048)
    __shared__ __align__(16) unsigned s_mem[5376];
    __shared__ unsigned short s_ptab[768];     // fused (ku,ti) -> packed edges

    int tid = threadIdx.x;
    if (blockIdx.x < NVB) {
        // ---- emit vertices (smem staging, proven) ----
        float* s_stage = (float*)s_mem;
        int v = blockIdx.x * 256 + tid;
        unsigned pk = (v < NV) ? g_pkl[v] : 0u;
        unsigned mask = pk & 0x7Fu;
        int excl = (int)(pk >> 7);
        int gbase = g_vblk[blockIdx.x];
        int total = g_vblk[blockIdx.x + 1] - gbase;

        if (mask) {
            float thr = (float)thrp[0];
            const float inv = 1.0f / 64.0f;
            int i = v / ND2;
            int r = v - i * ND2;
            int j = r / NDIM;
            int k = r - j * NDIM;
            float s0  = level[v] - thr;
            float p0x = (float)i * inv, p0y = (float)j * inv, p0z = (float)k * inv;
            int sp = excl * 3;
            #pragma unroll
            for (int d = 1; d < 8; ++d) {
                if (mask & (1u << (d - 1))) {
                    int di = d >> 2, dj = (d >> 1) & 1, dk = d & 1;
                    int w = v + di * ND2 + dj * NDIM + dk;
                    float s1 = level[w] - thr;
                    float rdenom = 1.0f / (s0 - s1);
                    float w0 = (-s1) * rdenom;
                    float w1 = s0 * rdenom;
                    s_stage[sp + 0] = p0x * w0 + (float)(i + di) * inv * w1;
                    s_stage[sp + 1] = p0y * w0 + (float)(j + dj) * inv * w1;
                    s_stage[sp + 2] = p0z * w0 + (float)(k + dk) * inv * w1;
                    sp += 3;
                }
            }
        }
        __syncthreads();
        float* dst = out + 3ll * gbase;
        int n = 3 * total;
        for (int x = tid; x < n; x += 256) dst[x] = s_stage[x];
    } else {
        // ---- emit faces: direct scattered stores (no staging) ----
        unsigned* s_pack = s_mem;              // 2048 words
        if (tid < 96) {
            int ku = tid >> 4, ti = tid & 15;
            #pragma unroll
            for (int s = 0; s < 6; ++s) {
                int le = d_tri[ti * 6 + s];
                unsigned short pv = 0;
                if (le >= 0) {
                    int ba = d_kuhn[ku * 4 + d_ea[le]];
                    int bb = d_kuhn[ku * 4 + d_eb[le]];
                    int lo = ba & bb;
                    int dd = ba ^ bb;
                    int bit = (((dd & 1) << 2) | (dd & 2) | ((dd >> 2) & 1)) - 1;
                    pv = (unsigned short)((lo << 3) | bit);
                }
                s_ptab[(ku * 16 + ti) * 8 + s] = pv;
            }
        }

        int cb = blockIdx.x - NVB;
        int cube = cb * 256 + tid;
        int ci = cube >> 12, cj = (cube >> 6) & 63, ck = cube & 63;
        int v000 = (ci * NDIM + cj) * NDIM + ck;
        unsigned occ8 = (unsigned)g_occ8[cube];      // 1 byte load, coalesced
        int ti6[6];
        unsigned sum = cube_codes(occ8, ti6);

        // corner cache with global vertex base folded in
        #pragma unroll
        for (int c = 0; c < 8; ++c) {
            int vc = v000 + corner_off(c);
            unsigned pk = g_pkl[vc];
            s_pack[c * 256 + tid] =
                (((unsigned)g_vblk[vc >> 8] + (pk >> 7)) << 7) | (pk & 0x7Fu);
        }

        unsigned total;
        unsigned run = blockScanExcl256<unsigned>(sum, total);  // syncs cover s_* writes

        unsigned long long blk = g_tblk[cb];
        int c1base = (int)(blk & 0xFFFFFFFFull);
        int c2base = (int)(blk >> 32);
        int F1 = g_F1;
        float* fout = out + 3ll * g_M;

        #pragma unroll
        for (int ku = 0; ku < 6; ++ku) {
            int ti = ti6[ku];
            int pc = __popc(ti);
            int nt = min(pc, 4 - pc);
            if (nt == 0) continue;
            int fbase;
            unsigned code;
            if (nt == 1) { fbase = c1base + (int)(run & 0xFFFFu);          code = 1u; }
            else         { fbase = F1 + 2 * (c2base + (int)(run >> 16));   code = 0x10000u; }
            const unsigned short* pt = &s_ptab[(ku * 16 + ti) * 8];
            int nent = 3 * nt;
            for (int e = 0; e < nent; ++e) {
                unsigned pe = pt[e];
                unsigned pk = s_pack[(pe >> 3) * 256 + tid];
                int vidx = (int)(pk >> 7) + __popc(pk & 0x7Fu & ((1u << (pe & 7)) - 1u));
                fout[3 * fbase + e] = (float)vidx;
            }
            run += code;
        }
    }
}

// ---------------- launch ----------------
extern "C" void kernel_launch(void* const* d_in, const int* in_sizes, int n_in,
                              void* d_out, int out_size) {
    const float* level = (const float*)d_in[0];
    const int*   thrp  = (const int*)d_in[3];
    float*       out   = (float*)d_out;
    (void)in_sizes; (void)n_in; (void)out_size;

    kCount<<<NBLK, 256>>>(level, thrp);
    kScan <<<1, 1024>>>();
    kEmit <<<NBLK, 256>>>(level, thrp, out);
}

// round 17
// speedup vs baseline: 1.7941x; 1.2797x over previous
#include <cuda_runtime.h>

#define NDIM 65
#define ND2  4225
#define NV   274625
#define NVB  1073            /* 256-vertex blocks            */
#define NC   262144          /* 64^3 cubes                   */
#define NCB  1024            /* cube blocks of 256           */
#define NBLK (NVB + NCB)     /* 2097 blocks in fused kernels */

// -------- scratch (device globals; no allocations allowed) --------
__device__ unsigned int       g_pkl[NV];      // (block-local excl << 7) | mask
__device__ int                g_vblk[NVB+1];  // block totals -> scanned bases (+M)
__device__ unsigned char      g_occ8[NC];     // per-cube 8-bit occupancy
__device__ unsigned long long g_tblk[NCB];    // lo32=c1 base, hi32=c2 base
__device__ int                g_M;
__device__ int                g_F1;

__device__ const signed char d_tri[96] = {
  -1,-1,-1,-1,-1,-1,  1,0,2,-1,-1,-1,  4,0,3,-1,-1,-1,  1,4,2,1,3,4,
   3,1,5,-1,-1,-1,    2,3,0,2,5,3,     1,4,0,1,5,4,     4,2,5,-1,-1,-1,
   4,5,2,-1,-1,-1,    4,1,0,4,5,1,     3,2,0,3,5,2,     1,3,5,-1,-1,-1,
   4,1,2,4,3,1,       3,0,4,-1,-1,-1,  2,0,1,-1,-1,-1, -1,-1,-1,-1,-1,-1};
__device__ const signed char d_ea[6]   = {0,0,0,1,1,2};
__device__ const signed char d_eb[6]   = {1,2,3,2,3,3};
__device__ const signed char d_kuhn[24] = {0,1,3,7, 0,3,2,7, 0,2,6,7,
                                           0,6,4,7, 0,4,5,7, 0,5,1,7};

__device__ __forceinline__ int corner_off(int b) {
    return (b & 1) * ND2 + ((b >> 1) & 1) * NDIM + ((b >> 2) & 1);
}

// ---------------- warp-shuffle block scan (256 threads) ----------------
template <typename T>
__device__ __forceinline__ T blockScanExcl256(T val, T& total) {
    unsigned lane = threadIdx.x & 31, w = threadIdx.x >> 5;
    T incl = val;
    #pragma unroll
    for (int o = 1; o < 32; o <<= 1) {
        T n = __shfl_up_sync(0xffffffffu, incl, o);
        if (lane >= o) incl += n;
    }
    __shared__ T ws[8];
    if (lane == 31) ws[w] = incl;
    __syncthreads();
    if (w == 0) {
        T x = (lane < 8) ? ws[lane] : T(0);
        #pragma unroll
        for (int o = 1; o < 8; o <<= 1) {
            T n = __shfl_up_sync(0xffffffffu, x, o);
            if (lane >= o) x += n;
        }
        if (lane < 8) ws[lane] = x;
    }
    __syncthreads();
    T base = (w > 0) ? ws[w - 1] : T(0);
    total = ws[7];
    return base + incl - val;
}

// per-cube tet codes from occ byte: packed (lo16=#1tri, hi16=#2tri), fills ti6[]
__device__ __forceinline__ unsigned cube_codes(unsigned occ8, int* ti6) {
    const int ka[6] = {1,3,2,6,4,5};
    const int kb[6] = {3,2,6,4,5,1};
    unsigned sum = 0;
    #pragma unroll
    for (int ku = 0; ku < 6; ++ku) {
        int ti = (int)(occ8 & 1u)
               | (int)(((occ8 >> ka[ku]) & 1u) << 1)
               | (int)(((occ8 >> kb[ku]) & 1u) << 2)
               | (int)(((occ8 >> 7) & 1u) << 3);
        ti6[ku] = ti;
        int pc = __popc(ti);
        int nt = min(pc, 4 - pc);
        sum += (nt == 1) ? 1u : ((nt == 2) ? 0x10000u : 0u);
    }
    return sum;
}

// ================= kCount: fused vertex masks + tet class counts (R10) =================
__global__ void kCount(const float* __restrict__ level, const int* __restrict__ thrp) {
    float thr = (float)thrp[0];
    if (blockIdx.x < NVB) {
        // ---- vertex branch ----
        int v = blockIdx.x * 256 + threadIdx.x;
        unsigned int mask = 0;
        if (v < NV) {
            int i = v / ND2;
            int r = v - i * ND2;
            int j = r / NDIM;
            int k = r - j * NDIM;
            bool o0 = (level[v] - thr) > 0.0f;
            #pragma unroll
            for (int d = 1; d < 8; ++d) {
                int di = d >> 2, dj = (d >> 1) & 1, dk = d & 1;
                if (i + di < NDIM && j + dj < NDIM && k + dk < NDIM) {
                    bool o1 = (level[v + di * ND2 + dj * NDIM + dk] - thr) > 0.0f;
                    if (o0 != o1) mask |= 1u << (d - 1);
                }
            }
        }
        int cnt = __popc(mask);
        int total;
        int excl = blockScanExcl256<int>(cnt, total);
        if (v < NV) g_pkl[v] = ((unsigned)excl << 7) | mask;
        if (threadIdx.x == 0) g_vblk[blockIdx.x] = total;
    } else {
        // ---- cube branch: classify tets straight from level, store occ8 ----
        int cb = blockIdx.x - NVB;
        int cube = cb * 256 + threadIdx.x;
        int ci = cube >> 12, cj = (cube >> 6) & 63, ck = cube & 63;
        int v000 = (ci * NDIM + cj) * NDIM + ck;
        unsigned occ8 = 0;
        #pragma unroll
        for (int b = 0; b < 8; ++b)
            occ8 |= ((level[v000 + corner_off(b)] - thr) > 0.0f ? 1u : 0u) << b;
        g_occ8[cube] = (unsigned char)occ8;
        int ti6[6];
        unsigned sum = cube_codes(occ8, ti6);

        #pragma unroll
        for (int o = 16; o > 0; o >>= 1) sum += __shfl_down_sync(0xffffffffu, sum, o);
        __shared__ unsigned ws[8];
        unsigned lane = threadIdx.x & 31, w = threadIdx.x >> 5;
        if (lane == 0) ws[w] = sum;
        __syncthreads();
        if (threadIdx.x == 0) {
            unsigned tot = 0;
            #pragma unroll
            for (int x = 0; x < 8; ++x) tot += ws[x];
            g_tblk[cb] = (unsigned long long)(tot & 0xFFFFu)
                       | ((unsigned long long)(tot >> 16) << 32);
        }
    }
}

// ================= kScan: both small scans (PDL secondary) =================
__global__ void kScan() {
    cudaGridDependencySynchronize();    // wait for kCount's results
    int t = threadIdx.x;
    unsigned lane = t & 31, w = t >> 5;

    { // vertex block bases (1073 ints, 2/thread)
        int i0 = 2 * t, i1 = 2 * t + 1;
        int e0 = (i0 < NVB) ? g_vblk[i0] : 0;
        int e1 = (i1 < NVB) ? g_vblk[i1] : 0;
        int val = e0 + e1;
        int incl = val;
        #pragma unroll
        for (int o = 1; o < 32; o <<= 1) {
            int n = __shfl_up_sync(0xffffffffu, incl, o);
            if (lane >= o) incl += n;
        }
        __shared__ int wsA[32];
        if (lane == 31) wsA[w] = incl;
        __syncthreads();
        if (w == 0) {
            int x = wsA[lane];
            #pragma unroll
            for (int o = 1; o < 32; o <<= 1) {
                int n = __shfl_up_sync(0xffffffffu, x, o);
                if (lane >= o) x += n;
            }
            wsA[lane] = x;
        }
        __syncthreads();
        int excl = ((w > 0) ? wsA[w - 1] : 0) + incl - val;
        if (i0 < NVB) g_vblk[i0] = excl;
        if (i1 < NVB) g_vblk[i1] = excl + e0;
        if (t == 1023) { g_M = excl + val; g_vblk[NVB] = excl + val; }
        __syncthreads();
    }

    { // tet block bases (1024 u64)
        unsigned long long val = g_tblk[t];
        unsigned long long incl = val;
        #pragma unroll
        for (int o = 1; o < 32; o <<= 1) {
            unsigned long long n = __shfl_up_sync(0xffffffffu, incl, o);
            if (lane >= o) incl += n;
        }
        __shared__ unsigned long long wsB[32];
        if (lane == 31) wsB[w] = incl;
        __syncthreads();
        if (w == 0) {
            unsigned long long x = wsB[lane];
            #pragma unroll
            for (int o = 1; o < 32; o <<= 1) {
                unsigned long long n = __shfl_up_sync(0xffffffffu, x, o);
                if (lane >= o) x += n;
            }
            wsB[lane] = x;
        }
        __syncthreads();
        unsigned long long excl = ((w > 0) ? wsB[w - 1] : 0ull) + incl - val;
        g_tblk[t] = excl;
        if (t == 1023) g_F1 = (int)((excl + val) & 0xFFFFFFFFull);
    }
}

// ================= kEmit: fused verts + faces (PDL secondary) =================
__global__ void kEmit(const float* __restrict__ level, const int* __restrict__ thrp,
                      float* __restrict__ out) {
    __shared__ float          s_stage[9216];   // verts (<=5376) or faces (<=9216)
    __shared__ unsigned       s_pack[8 * 256]; // face-branch corner cache
    __shared__ unsigned short s_ptab[768];     // fused (ku,ti) -> packed edges

    int tid = threadIdx.x;
    bool isFace = (blockIdx.x >= NVB);

    // --- prologue with no upstream dependency: build constant table ---
    if (isFace && tid < 96) {
        int ku = tid >> 4, ti = tid & 15;
        #pragma unroll
        for (int s = 0; s < 6; ++s) {
            int le = d_tri[ti * 6 + s];
            unsigned short pv = 0;
            if (le >= 0) {
                int ba = d_kuhn[ku * 4 + d_ea[le]];
                int bb = d_kuhn[ku * 4 + d_eb[le]];
                int lo = ba & bb;
                int dd = ba ^ bb;
                int bit = (((dd & 1) << 2) | (dd & 2) | ((dd >> 2) & 1)) - 1;
                pv = (unsigned short)((lo << 3) | bit);
            }
            s_ptab[(ku * 16 + ti) * 8 + s] = pv;
        }
    }

    cudaGridDependencySynchronize();    // wait for kScan (and transitively kCount)

    if (!isFace) {
        // ---- emit vertices ----
        int v = blockIdx.x * 256 + tid;
        unsigned pk = (v < NV) ? g_pkl[v] : 0u;
        unsigned mask = pk & 0x7Fu;
        int excl = (int)(pk >> 7);
        int gbase = g_vblk[blockIdx.x];
        int total = g_vblk[blockIdx.x + 1] - gbase;

        if (mask) {
            float thr = (float)thrp[0];
            const float inv = 1.0f / 64.0f;
            int i = v / ND2;
            int r = v - i * ND2;
            int j = r / NDIM;
            int k = r - j * NDIM;
            float s0  = level[v] - thr;
            float p0x = (float)i * inv, p0y = (float)j * inv, p0z = (float)k * inv;
            int sp = excl * 3;
            #pragma unroll
            for (int d = 1; d < 8; ++d) {
                if (mask & (1u << (d - 1))) {
                    int di = d >> 2, dj = (d >> 1) & 1, dk = d & 1;
                    int w = v + di * ND2 + dj * NDIM + dk;
                    float s1 = level[w] - thr;
                    float rdenom = 1.0f / (s0 - s1);
                    float w0 = (-s1) * rdenom;
                    float w1 = s0 * rdenom;
                    s_stage[sp + 0] = p0x * w0 + (float)(i + di) * inv * w1;
                    s_stage[sp + 1] = p0y * w0 + (float)(j + dj) * inv * w1;
                    s_stage[sp + 2] = p0z * w0 + (float)(k + dk) * inv * w1;
                    sp += 3;
                }
            }
        }
        __syncthreads();
        float* dst = out + 3ll * gbase;
        int n = 3 * total;
        for (int x = tid; x < n; x += 256) dst[x] = s_stage[x];
    } else {
        // ---- emit faces ----
        int cb = blockIdx.x - NVB;
        int cube = cb * 256 + tid;
        int ci = cube >> 12, cj = (cube >> 6) & 63, ck = cube & 63;
        int v000 = (ci * NDIM + cj) * NDIM + ck;
        unsigned occ8 = (unsigned)g_occ8[cube];      // 1 byte load, coalesced
        int ti6[6];
        unsigned sum = cube_codes(occ8, ti6);

        // corner cache with global vertex base folded in
        #pragma unroll
        for (int c = 0; c < 8; ++c) {
            int vc = v000 + corner_off(c);
            unsigned pk = g_pkl[vc];
            s_pack[c * 256 + tid] =
                (((unsigned)g_vblk[vc >> 8] + (pk >> 7)) << 7) | (pk & 0x7Fu);
        }

        unsigned total;
        unsigned run = blockScanExcl256<unsigned>(sum, total);  // syncs cover s_* writes
        int total1 = (int)(total & 0xFFFFu);
        int total2 = (int)(total >> 16);

        // build faces into smem at block-local offsets
        #pragma unroll
        for (int ku = 0; ku < 6; ++ku) {
            int ti = ti6[ku];
            int pc = __popc(ti);
            int nt = min(pc, 4 - pc);
            if (nt == 0) continue;
            int sp;
            unsigned code;
            if (nt == 1) { sp = 3 * (int)(run & 0xFFFFu);           code = 1u; }
            else         { sp = 3 * total1 + 6 * (int)(run >> 16);  code = 0x10000u; }
            const unsigned short* pt = &s_ptab[(ku * 16 + ti) * 8];
            int nent = 3 * nt;
            for (int e = 0; e < nent; ++e) {
                unsigned pe = pt[e];
                unsigned pk = s_pack[(pe >> 3) * 256 + tid];
                int vidx = (int)(pk >> 7) + __popc(pk & 0x7Fu & ((1u << (pe & 7)) - 1u));
                s_stage[sp + e] = (float)vidx;
            }
            run += code;
        }
        __syncthreads();

        unsigned long long blk = g_tblk[cb];
        int c1base = (int)(blk & 0xFFFFFFFFull);
        int c2base = (int)(blk >> 32);
        float* fout = out + 3ll * g_M;

        float* dst1 = fout + 3ll * c1base;
        int n1 = 3 * total1;
        for (int x = tid; x < n1; x += 256) dst1[x] = s_stage[x];
        float* dst2 = fout + 3ll * (g_F1 + 2ll * c2base);
        int n2 = 6 * total2;
        const float* src2 = s_stage + n1;
        for (int x = tid; x < n2; x += 256) dst2[x] = src2[x];
    }
}

// ---------------- launch (PDL: overlap launch gaps) ----------------
extern "C" void kernel_launch(void* const* d_in, const int* in_sizes, int n_in,
                              void* d_out, int out_size) {
    const float* level = (const float*)d_in[0];
    const int*   thrp  = (const int*)d_in[3];
    float*       out   = (float*)d_out;
    (void)in_sizes; (void)n_in; (void)out_size;

    kCount<<<NBLK, 256>>>(level, thrp);

    cudaLaunchAttribute attr[1];
    attr[0].id = cudaLaunchAttributeProgrammaticStreamSerialization;
    attr[0].val.programmaticStreamSerializationAllowed = 1;

    {
        cudaLaunchConfig_t cfg = {};
        cfg.gridDim = dim3(1, 1, 1);
        cfg.blockDim = dim3(1024, 1, 1);
        cfg.attrs = attr;
        cfg.numAttrs = 1;
        cudaLaunchKernelEx(&cfg, kScan);
    }
    {
        cudaLaunchConfig_t cfg = {};
        cfg.gridDim = dim3(NBLK, 1, 1);
        cfg.blockDim = dim3(256, 1, 1);
        cfg.attrs = attr;
        cfg.numAttrs = 1;
        cudaLaunchKernelEx(&cfg, kEmit, level, thrp, out);
    }
}